// round 1
// baseline (speedup 1.0000x reference)
#include <cuda_runtime.h>
#include <cstdint>

// Problem constants
constexpr int kB  = 16;
constexpr int kTx = 256;
constexpr int kTy = 2048;
constexpr int kC  = 80;
constexpr int kH  = 256;
#define NEGV (-1e9f)

// ---------------- scratch (__device__ globals; no allocation) ----------------
__device__ float    g_I   [kB * kC * kTx];       // inv_var,   layout [b][c][x]
__device__ float    g_A2  [kB * kC * kTx];       // -2*mu*iv,  layout [b][c][x]
__device__ float    g_bias[kB * kTx];            // -(0.5/C)*(t3 + sum_c ls)
__device__ unsigned g_diagT[kB * kTx * 64];      // diag bits, [b][row][word(t/32)]
__device__ int      g_cum [kB * (kTx + 1)];      // exclusive cumsum of durations
__device__ int      g_xidx[kB * kTy];            // per-frame row index, -1 beyond y_len

// ---------------- Kernel 0: per-(b,x) precompute -----------------------------
__global__ void k_prep(const float* __restrict__ mu, const float* __restrict__ ls) {
    int b = blockIdx.x;
    int x = threadIdx.x;
    const float* mub = mu + (size_t)b * kC * kTx + x;
    const float* lsb = ls + (size_t)b * kC * kTx + x;
    float t3 = 0.f, sls = 0.f;
    #pragma unroll 4
    for (int c = 0; c < kC; c++) {
        float m  = mub[c * kTx];
        float l  = lsb[c * kTx];
        float iv = expf(-2.0f * l);
        g_I [(b * kC + c) * kTx + x] = iv;
        g_A2[(b * kC + c) * kTx + x] = -2.0f * m * iv;
        t3  += m * m * iv;
        sls += l;
    }
    g_bias[b * kTx + x] = -(0.5f / (float)kC) * (t3 + sls);
}

// ---------------- Kernel 1: logp GEMM  ----------------------------------------
// logp[b][x][t] = -(0.5/C) * sum_c ( iv*y^2 + a2*y ) + bias[b][x]
// Tile: 64 x-rows  x  128 t-cols per block, 128 threads, 8x8 microtile.
// smem: syT [80][132] (y transposed, padded), sI/sA [16][64] staged per k-chunk.
constexpr int SMEM_LOGP = (kC * 132 + 2 * 16 * 64) * 4;  // 50432 bytes

__global__ void __launch_bounds__(128) k_logp(const float* __restrict__ y,
                                              float* __restrict__ out_logp) {
    extern __shared__ float smA[];
    float* syT = smA;                 // 80*132 floats
    float* sI  = smA + kC * 132;      // 16*64
    float* sA  = sI + 16 * 64;        // 16*64

    int b  = blockIdx.z;
    int x0 = blockIdx.y * 64;
    int t0 = blockIdx.x * 128;
    int tid = threadIdx.x;
    int tx = tid & 7;        // x group: x = x0 + tx*8 + xi
    int ty = tid >> 3;       // t group: t = t0 + ty*8 + ti

    // stage y tile transposed: syT[c][t] = y[b][t0+t][c]
    const float* yb = y + ((size_t)b * kTy + t0) * kC;
    for (int e = tid; e < 128 * kC; e += 128) {
        int t = e / kC;
        int c = e - t * kC;
        syT[c * 132 + t] = yb[(size_t)t * kC + c];
    }

    float acc[8][8];
    #pragma unroll
    for (int i = 0; i < 8; i++)
        #pragma unroll
        for (int j = 0; j < 8; j++) acc[i][j] = 0.f;

    for (int kc = 0; kc < 5; kc++) {       // 5 chunks of 16 c's
        __syncthreads();
        for (int e = tid; e < 16 * 64; e += 128) {
            int cc = e >> 6, xx = e & 63;
            int gidx = (b * kC + kc * 16 + cc) * kTx + x0 + xx;
            sI[e] = g_I [gidx];
            sA[e] = g_A2[gidx];
        }
        __syncthreads();
        #pragma unroll
        for (int cc = 0; cc < 16; cc++) {
            float iv[8], a2[8], yv[8];
            float4 v;
            v = *reinterpret_cast<const float4*>(&sI[cc * 64 + tx * 8]);
            iv[0] = v.x; iv[1] = v.y; iv[2] = v.z; iv[3] = v.w;
            v = *reinterpret_cast<const float4*>(&sI[cc * 64 + tx * 8 + 4]);
            iv[4] = v.x; iv[5] = v.y; iv[6] = v.z; iv[7] = v.w;
            v = *reinterpret_cast<const float4*>(&sA[cc * 64 + tx * 8]);
            a2[0] = v.x; a2[1] = v.y; a2[2] = v.z; a2[3] = v.w;
            v = *reinterpret_cast<const float4*>(&sA[cc * 64 + tx * 8 + 4]);
            a2[4] = v.x; a2[5] = v.y; a2[6] = v.z; a2[7] = v.w;
            const float* yrow = &syT[(kc * 16 + cc) * 132 + ty * 8];
            v = *reinterpret_cast<const float4*>(yrow);
            yv[0] = v.x; yv[1] = v.y; yv[2] = v.z; yv[3] = v.w;
            v = *reinterpret_cast<const float4*>(yrow + 4);
            yv[4] = v.x; yv[5] = v.y; yv[6] = v.z; yv[7] = v.w;
            #pragma unroll
            for (int xi = 0; xi < 8; xi++)
                #pragma unroll
                for (int ti = 0; ti < 8; ti++) {
                    float tmp = __fmaf_rn(iv[xi], yv[ti], a2[xi]);
                    acc[xi][ti] = __fmaf_rn(yv[ti], tmp, acc[xi][ti]);
                }
        }
    }

    const float SC = -0.5f / (float)kC;
    #pragma unroll
    for (int xi = 0; xi < 8; xi++) {
        int x = x0 + tx * 8 + xi;
        float bsv = g_bias[b * kTx + x];
        float* o = out_logp + ((size_t)(b * kTx + x)) * kTy + t0 + ty * 8;
        float4 r;
        r.x = __fmaf_rn(SC, acc[xi][0], bsv);
        r.y = __fmaf_rn(SC, acc[xi][1], bsv);
        r.z = __fmaf_rn(SC, acc[xi][2], bsv);
        r.w = __fmaf_rn(SC, acc[xi][3], bsv);
        *reinterpret_cast<float4*>(o) = r;
        r.x = __fmaf_rn(SC, acc[xi][4], bsv);
        r.y = __fmaf_rn(SC, acc[xi][5], bsv);
        r.z = __fmaf_rn(SC, acc[xi][6], bsv);
        r.w = __fmaf_rn(SC, acc[xi][7], bsv);
        *reinterpret_cast<float4*>(o + 4) = r;
    }
}

// ---------------- Kernel 2: MAS forward (Viterbi scan) ------------------------
// One warp per batch. Lane owns rows [lane*8, lane*8+8). diag bits stored
// transposed: g_diagT[b][row][t/32] bit (t%32).
__device__ __forceinline__ void mas_step(float v[8], unsigned bits[8],
                                         const bool ok[8], const float col[8],
                                         int sha, int lane) {
    float sh = __shfl_up_sync(0xffffffffu, v[7], 1);
    if (lane == 0) sh = NEGV;
    float pv = sh;
    #pragma unroll
    for (int k = 0; k < 8; k++) {
        float cur = v[k];
        if (pv > cur) bits[k] |= (1u << sha);
        float m = fmaxf(pv, cur) + col[k];
        v[k] = ok[k] ? m : NEGV;
        pv = cur;
    }
}

__global__ void k_mas_fwd(const float* __restrict__ logp,
                          const int* __restrict__ xlv,
                          const int* __restrict__ ylv) {
    int b = blockIdx.x;
    int lane = threadIdx.x;
    const float* lp = logp + (size_t)b * kTx * kTy + (size_t)lane * 8 * kTy;
    int xlen = xlv[b];
    int ylen = ylv[b];

    float v[8];
    bool ok[8];
    #pragma unroll
    for (int k = 0; k < 8; k++) {
        int i = lane * 8 + k;
        v[k] = (i == 0) ? 0.f : NEGV;
        ok[k] = (i < xlen);
    }
    unsigned bits[8] = {0u, 0u, 0u, 0u, 0u, 0u, 0u, 0u};
    unsigned* dout = g_diagT + (size_t)(b * kTx + lane * 8) * 64;

    int T32 = (ylen + 31) & ~31;   // <= 2048
    for (int t0 = 0; t0 < T32; t0 += 4) {
        float col[4][8];
        #pragma unroll
        for (int k = 0; k < 8; k++) {
            float4 q = *reinterpret_cast<const float4*>(lp + (size_t)k * kTy + t0);
            col[0][k] = q.x; col[1][k] = q.y; col[2][k] = q.z; col[3][k] = q.w;
        }
        #pragma unroll
        for (int j = 0; j < 4; j++)
            mas_step(v, bits, ok, col[j], (t0 + j) & 31, lane);

        if (((t0 + 4) & 31) == 0) {
            int w = t0 >> 5;
            #pragma unroll
            for (int k = 0; k < 8; k++) { dout[k * 64 + w] = bits[k]; bits[k] = 0u; }
        }
    }
}

// ---------------- Kernel 3: backtrace -> durations, cumsum, frame index -------
__global__ void k_mas_bwd(const int* __restrict__ xlv, const int* __restrict__ ylv,
                          float* __restrict__ dr_out) {
    extern __shared__ unsigned sdiag[];          // 256*64 = 16384 words (64KB)
    __shared__ int s_dr[kTx];
    __shared__ int s_cum[kTx + 1];
    int b = blockIdx.x;
    int tid = threadIdx.x;

    const unsigned* gsrc = g_diagT + (size_t)b * kTx * 64;
    for (int e = tid; e < kTx * 64; e += blockDim.x) sdiag[e] = gsrc[e];
    s_dr[tid] = 0;
    __syncthreads();

    if (tid == 0) {
        int xlen = xlv[b], ylen = ylv[b];
        int i = xlen - 1;
        int t = ylen - 1;
        while (i > 0 && t >= 0) {
            int w = t >> 5;
            unsigned word = sdiag[i * 64 + w] & (0xFFFFFFFFu >> (31 - (t & 31)));
            int tp = -1;
            while (true) {
                if (word) { tp = (w << 5) + (31 - __clz(word)); break; }
                if (--w < 0) break;
                word = sdiag[i * 64 + w];
            }
            if (tp < 0) { s_dr[i] = t + 1; t = -1; break; }
            s_dr[i] = t - tp + 1;
            t = tp - 1;
            i--;
        }
        if (i == 0 && t >= 0) s_dr[0] = t + 1;  // row-0 bits ignored (clamp semantics)
    }
    __syncthreads();

    if (tid == 0) {
        int a = 0;
        for (int x = 0; x < kTx; x++) { s_cum[x] = a; a += s_dr[x]; }
        s_cum[kTx] = a;
    }
    __syncthreads();

    dr_out[b * kTx + tid] = (float)s_dr[tid];
    g_cum[b * (kTx + 1) + tid] = s_cum[tid];
    if (tid == 0) g_cum[b * (kTx + 1) + kTx] = s_cum[kTx];

    int lo = s_cum[tid], hi = s_cum[tid + 1];
    for (int t = lo; t < hi; t++) g_xidx[b * kTy + t] = tid;
    int total = s_cum[kTx];
    for (int t = total + tid; t < kTy; t += blockDim.x) g_xidx[b * kTy + t] = -1;
}

// ---------------- Kernel 4: hard alignment attn[b][x][t] ----------------------
__global__ void k_attn(float* __restrict__ attn) {
    int x = blockIdx.x, b = blockIdx.y, tid = threadIdx.x;
    int lo = g_cum[b * (kTx + 1) + x];
    int hi = g_cum[b * (kTx + 1) + x + 1];
    float* o = attn + ((size_t)(b * kTx + x)) * kTy + tid * 8;
    int t = tid * 8;
    float4 r;
    r.x = (t + 0 >= lo && t + 0 < hi) ? 1.f : 0.f;
    r.y = (t + 1 >= lo && t + 1 < hi) ? 1.f : 0.f;
    r.z = (t + 2 >= lo && t + 2 < hi) ? 1.f : 0.f;
    r.w = (t + 3 >= lo && t + 3 < hi) ? 1.f : 0.f;
    *reinterpret_cast<float4*>(o) = r;
    r.x = (t + 4 >= lo && t + 4 < hi) ? 1.f : 0.f;
    r.y = (t + 5 >= lo && t + 5 < hi) ? 1.f : 0.f;
    r.z = (t + 6 >= lo && t + 6 < hi) ? 1.f : 0.f;
    r.w = (t + 7 >= lo && t + 7 < hi) ? 1.f : 0.f;
    *reinterpret_cast<float4*>(o + 4) = r;
}

// ---------------- Kernel 5: o_en_ex gather  -----------------------------------
__global__ void k_gather(const float* __restrict__ en, float* __restrict__ oex) {
    __shared__ __align__(16) float srow[kTx];
    __shared__ __align__(16) int   sidx[kTy];
    int h = blockIdx.x, b = blockIdx.y, tid = threadIdx.x;

    srow[tid] = en[((size_t)(b * kH + h)) * kTx + tid];
    const int* xsrc = g_xidx + b * kTy;
    for (int e = tid; e < kTy; e += 256)
        sidx[e] = xsrc[e];
    __syncthreads();

    float* o = oex + ((size_t)(b * kH + h)) * kTy + tid * 8;
    int4 ia = *reinterpret_cast<const int4*>(&sidx[tid * 8]);
    int4 ib = *reinterpret_cast<const int4*>(&sidx[tid * 8 + 4]);
    float4 r;
    r.x = (ia.x >= 0) ? srow[ia.x] : 0.f;
    r.y = (ia.y >= 0) ? srow[ia.y] : 0.f;
    r.z = (ia.z >= 0) ? srow[ia.z] : 0.f;
    r.w = (ia.w >= 0) ? srow[ia.w] : 0.f;
    *reinterpret_cast<float4*>(o) = r;
    r.x = (ib.x >= 0) ? srow[ib.x] : 0.f;
    r.y = (ib.y >= 0) ? srow[ib.y] : 0.f;
    r.z = (ib.z >= 0) ? srow[ib.z] : 0.f;
    r.w = (ib.w >= 0) ? srow[ib.w] : 0.f;
    *reinterpret_cast<float4*>(o + 4) = r;
}

// ---------------- launch -------------------------------------------------------
extern "C" void kernel_launch(void* const* d_in, const int* in_sizes, int n_in,
                              void* d_out, int out_size) {
    const float* en = (const float*)d_in[0];   // [B,H,Tx]
    const float* mu = (const float*)d_in[1];   // [B,C,Tx]
    const float* ls = (const float*)d_in[2];   // [B,C,Tx]
    const float* y  = (const float*)d_in[3];   // [B,Ty,C]
    const int*   xl = (const int*)d_in[4];     // [B]
    const int*   yl = (const int*)d_in[5];     // [B]

    float* out   = (float*)d_out;
    float* o_en  = out;                                     // B*H*Ty
    float* attn  = o_en + (size_t)kB * kH * kTy;            // B*Tx*Ty
    float* dr    = attn + (size_t)kB * kTx * kTy;           // B*Tx
    float* logp  = dr + (size_t)kB * kTx;                   // B*Tx*Ty

    cudaFuncSetAttribute(k_logp, cudaFuncAttributeMaxDynamicSharedMemorySize, SMEM_LOGP);
    cudaFuncSetAttribute(k_mas_bwd, cudaFuncAttributeMaxDynamicSharedMemorySize, 65536);

    k_prep<<<kB, kTx>>>(mu, ls);
    k_logp<<<dim3(kTy / 128, kTx / 64, kB), 128, SMEM_LOGP>>>(y, logp);
    k_mas_fwd<<<kB, 32>>>(logp, xl, yl);
    k_mas_bwd<<<kB, 256, 65536>>>(xl, yl, dr);
    k_attn<<<dim3(kTx, kB), 256>>>(attn);
    k_gather<<<dim3(kH, kB), 256>>>(en, o_en);
}

// round 2
// speedup vs baseline: 1.9492x; 1.9492x over previous
#include <cuda_runtime.h>
#include <cstdint>

constexpr int kB  = 16;
constexpr int kTx = 256;
constexpr int kTy = 2048;
constexpr int kC  = 80;
constexpr int kC2 = kC / 2;   // 40 c-pairs
constexpr int kH  = 256;
#define NEGV (-1e9f)
typedef unsigned long long ull;

// ---------------- scratch (__device__ globals) --------------------------------
__device__ float2 g_Ip  [kB * kC2 * kTx];            // (iv[2c], iv[2c+1]) per x
__device__ float2 g_A2p [kB * kC2 * kTx];            // (-2*mu*iv) pairs
__device__ float  g_bias[kB * kTx];
__device__ float  g_logpT[(size_t)kB * kTy * kTx + 16 * kTx];  // [b][t][x] + pad
__device__ int    g_cum [kB * 257];
__device__ int    g_xidx[kB * kTy];

#define FMA2(d,a,b,c) asm("fma.rn.f32x2 %0, %1, %2, %3;" : "=l"(d) : "l"(a), "l"(b), "l"(c))

// ---------------- Kernel 0: per-(b,x) precompute ------------------------------
__global__ void k_prep(const float* __restrict__ mu, const float* __restrict__ ls) {
    int b = blockIdx.x;
    int x = threadIdx.x;
    const float* mub = mu + (size_t)b * kC * kTx + x;
    const float* lsb = ls + (size_t)b * kC * kTx + x;
    float t3 = 0.f, sls = 0.f;
    #pragma unroll 4
    for (int c2 = 0; c2 < kC2; c2++) {
        float m0 = mub[(2 * c2) * kTx],     m1 = mub[(2 * c2 + 1) * kTx];
        float l0 = lsb[(2 * c2) * kTx],     l1 = lsb[(2 * c2 + 1) * kTx];
        float iv0 = expf(-2.0f * l0),       iv1 = expf(-2.0f * l1);
        g_Ip [(b * kC2 + c2) * kTx + x] = make_float2(iv0, iv1);
        g_A2p[(b * kC2 + c2) * kTx + x] = make_float2(-2.0f * m0 * iv0, -2.0f * m1 * iv1);
        t3  += m0 * m0 * iv0 + m1 * m1 * iv1;
        sls += l0 + l1;
    }
    g_bias[b * kTx + x] = -(0.5f / (float)kC) * (t3 + sls);
}

// ---------------- Kernel 1: logp GEMM via fma.rn.f32x2 -------------------------
// Tile 64x × 128t per block, 128 threads, 8×8 microtile, packed over c-pairs.
// smem (ull units), groups of 8 ull padded to 10 (80B stride -> conflict-free):
//   sy2: [40 c2][16 tgrp * 10]   = 6400 ull
//   sI2: [40 c2][ 8 xgrp * 10]   = 3200 ull
//   sA2: same                    = 3200 ull
constexpr int SY_OFF  = 0;
constexpr int SI_OFF  = 40 * 160;
constexpr int SA_OFF  = SI_OFF + 40 * 80;
constexpr int SMEM_ULL = SA_OFF + 40 * 80;          // 12800 ull = 102400 B

__global__ void __launch_bounds__(128) k_logp(const float* __restrict__ y,
                                              float* __restrict__ out_logp) {
    extern __shared__ ull sm[];
    int b  = blockIdx.z;
    int x0 = blockIdx.y * 64;
    int t0 = blockIdx.x * 128;
    int tid = threadIdx.x;
    int tx = tid & 7;        // x-group
    int ty = tid >> 3;       // t-group (16 groups of 8 t)

    // stage y pairs: sy2[c2][t] = (y[t][2c2], y[t][2c2+1])
    for (int e = tid; e < 128 * kC2; e += 128) {
        int c2 = e % kC2;
        int t  = e / kC2;
        float2 v = *(const float2*)(y + ((size_t)(b * kTy + t0 + t)) * kC + 2 * c2);
        sm[SY_OFF + c2 * 160 + (t >> 3) * 10 + (t & 7)] = *(ull*)&v;
    }
    // stage iv / a2 pairs
    for (int e = tid; e < kC2 * 64; e += 128) {
        int c2 = e >> 6, xx = e & 63;
        int sidx = c2 * 80 + (xx >> 3) * 10 + (xx & 7);
        float2 vi = g_Ip [(b * kC2 + c2) * kTx + x0 + xx];
        float2 va = g_A2p[(b * kC2 + c2) * kTx + x0 + xx];
        sm[SI_OFF + sidx] = *(ull*)&vi;
        sm[SA_OFF + sidx] = *(ull*)&va;
    }
    __syncthreads();

    ull acc[8][8];
    #pragma unroll
    for (int i = 0; i < 8; i++)
        #pragma unroll
        for (int j = 0; j < 8; j++) acc[i][j] = 0ull;

    #pragma unroll 2
    for (int c2 = 0; c2 < kC2; c2++) {
        ull ivp[8], a2p[8], yvp[8];
        const ulonglong2* pi = (const ulonglong2*)(sm + SI_OFF + c2 * 80 + tx * 10);
        const ulonglong2* pa = (const ulonglong2*)(sm + SA_OFF + c2 * 80 + tx * 10);
        const ulonglong2* py = (const ulonglong2*)(sm + SY_OFF + c2 * 160 + ty * 10);
        #pragma unroll
        for (int i = 0; i < 4; i++) {
            ulonglong2 q;
            q = pi[i]; ivp[2 * i] = q.x; ivp[2 * i + 1] = q.y;
            q = pa[i]; a2p[2 * i] = q.x; a2p[2 * i + 1] = q.y;
            q = py[i]; yvp[2 * i] = q.x; yvp[2 * i + 1] = q.y;
        }
        #pragma unroll
        for (int xi = 0; xi < 8; xi++)
            #pragma unroll
            for (int ti = 0; ti < 8; ti++) {
                ull tmp;
                FMA2(tmp, ivp[xi], yvp[ti], a2p[xi]);
                FMA2(acc[xi][ti], yvp[ti], tmp, acc[xi][ti]);
            }
    }

    // epilogue: res = SC * (lo+hi) + bias
    const float SC = -0.5f / (float)kC;
    float res[8][8];
    float bsv[8];
    #pragma unroll
    for (int xi = 0; xi < 8; xi++) {
        bsv[xi] = g_bias[b * kTx + x0 + tx * 8 + xi];
        #pragma unroll
        for (int ti = 0; ti < 8; ti++) {
            float2 p = *(float2*)&acc[xi][ti];
            res[xi][ti] = __fmaf_rn(SC, p.x + p.y, bsv[xi]);
        }
    }
    // store logp [b][x][t]
    #pragma unroll
    for (int xi = 0; xi < 8; xi++) {
        int x = x0 + tx * 8 + xi;
        float* o = out_logp + ((size_t)(b * kTx + x)) * kTy + t0 + ty * 8;
        float4 r;
        r.x = res[xi][0]; r.y = res[xi][1]; r.z = res[xi][2]; r.w = res[xi][3];
        *(float4*)o = r;
        r.x = res[xi][4]; r.y = res[xi][5]; r.z = res[xi][6]; r.w = res[xi][7];
        *(float4*)(o + 4) = r;
    }
    // store logpT [b][t][x]
    #pragma unroll
    for (int ti = 0; ti < 8; ti++) {
        int t = t0 + ty * 8 + ti;
        float* o = g_logpT + ((size_t)b * kTy + t) * kTx + x0 + tx * 8;
        float4 r;
        r.x = res[0][ti]; r.y = res[1][ti]; r.z = res[2][ti]; r.w = res[3][ti];
        *(float4*)o = r;
        r.x = res[4][ti]; r.y = res[5][ti]; r.z = res[6][ti]; r.w = res[7][ti];
        *(float4*)(o + 4) = r;
    }
}

// ---------------- Kernel 2: fused MAS forward + backtrace + durations ----------
// Grid 16 blocks x 256 threads. Warp 0 does the Viterbi scan with diag bits in
// smem (layout [word][row] for conflict-free vectorized flushes). Then lane 0
// backtraces from smem, and the whole block does scan + output writes.
__global__ void __launch_bounds__(256) k_mas(const int* __restrict__ xlv,
                                             const int* __restrict__ ylv,
                                             float* __restrict__ dr_out) {
    extern __shared__ unsigned sdiag[];       // 64 * 256 words = 64KB
    __shared__ int s_dr[kTx];
    __shared__ int s_wsum[8];
    __shared__ int s_tot;
    int b = blockIdx.x;
    int tid = threadIdx.x;

    s_dr[tid] = 0;

    if (tid < 32) {
        int lane = tid;
        const float* lp = g_logpT + (size_t)b * kTy * kTx + lane * 8;
        float4 buf[4][4][2];
        #define LG(gv, r)                                                        \
            {                                                                    \
                const float* p_ = lp + (size_t)((gv) * 4) * kTx;                 \
                _Pragma("unroll")                                                \
                for (int j_ = 0; j_ < 4; j_++) {                                 \
                    buf[r][j_][0] = *(const float4*)(p_ + j_ * kTx);             \
                    buf[r][j_][1] = *(const float4*)(p_ + j_ * kTx + 4);         \
                }                                                                \
            }
        LG(0, 0); LG(1, 1); LG(2, 2);

        float v[8];
        unsigned bits[8];
        #pragma unroll
        for (int k = 0; k < 8; k++) {
            v[k] = (lane == 0 && k == 0) ? 0.f : NEGV;
            bits[k] = 0u;
        }

        #pragma unroll 8
        for (int g = 0; g < 512; g++) {
            LG(g + 3, (g + 3) & 3);
            #pragma unroll
            for (int j = 0; j < 4; j++) {
                unsigned m = 1u << (((g & 7) * 4 + j) & 31);
                float4 a = buf[g & 3][j][0];
                float4 c4 = buf[g & 3][j][1];
                float col[8] = {a.x, a.y, a.z, a.w, c4.x, c4.y, c4.z, c4.w};
                float sh = __shfl_up_sync(0xffffffffu, v[7], 1);
                if (lane == 0) sh = NEGV;
                float pv = sh;
                #pragma unroll
                for (int k = 0; k < 8; k++) {
                    float cur = v[k];
                    if (pv > cur) bits[k] |= m;
                    v[k] = fmaxf(pv, cur) + col[k];
                    pv = cur;
                }
            }
            if (((g + 1) & 7) == 0) {
                int w = g >> 3;
                *(uint4*)&sdiag[w * kTx + lane * 8] =
                    make_uint4(bits[0], bits[1], bits[2], bits[3]);
                *(uint4*)&sdiag[w * kTx + lane * 8 + 4] =
                    make_uint4(bits[4], bits[5], bits[6], bits[7]);
                #pragma unroll
                for (int k = 0; k < 8; k++) bits[k] = 0u;
            }
        }
        #undef LG
    }
    __syncthreads();

    // serial backtrace on lane 0
    if (tid == 0) {
        int xlen = xlv[b], ylen = ylv[b];
        int i = xlen - 1;
        int t = ylen - 1;
        while (i > 0 && t >= 0) {
            int w = t >> 5;
            unsigned word = sdiag[w * kTx + i] & (0xFFFFFFFFu >> (31 - (t & 31)));
            int tp = -1;
            while (true) {
                if (word) { tp = (w << 5) + (31 - __clz(word)); break; }
                if (--w < 0) break;
                word = sdiag[w * kTx + i];
            }
            if (tp < 0) { s_dr[i] = t + 1; t = -1; break; }
            s_dr[i] = t - tp + 1;
            t = tp - 1;
            i--;
        }
        if (i == 0 && t >= 0) s_dr[0] = t + 1;
    }
    __syncthreads();

    // block scan of s_dr -> exclusive cumsum
    int dv = s_dr[tid];
    int lane = tid & 31, wid = tid >> 5;
    int xs = dv;
    #pragma unroll
    for (int off = 1; off < 32; off <<= 1) {
        int n = __shfl_up_sync(0xffffffffu, xs, off);
        if (lane >= off) xs += n;
    }
    if (lane == 31) s_wsum[wid] = xs;
    __syncthreads();
    if (tid == 0) {
        int a = 0;
        #pragma unroll
        for (int w = 0; w < 8; w++) { int tmp = s_wsum[w]; s_wsum[w] = a; a += tmp; }
        s_tot = a;
    }
    __syncthreads();
    int incl = xs + s_wsum[wid];
    int excl = incl - dv;

    dr_out[b * kTx + tid] = (float)dv;
    g_cum[b * 257 + tid] = excl;
    if (tid == kTx - 1) g_cum[b * 257 + kTx] = incl;

    for (int t = excl; t < excl + dv; t++) g_xidx[b * kTy + t] = tid;
    int total = s_tot;
    for (int t = total + tid; t < kTy; t += 256) g_xidx[b * kTy + t] = -1;
}

// ---------------- Kernel 3: hard alignment attn[b][x][t] -----------------------
__global__ void k_attn(float* __restrict__ attn) {
    int x = blockIdx.x, b = blockIdx.y, tid = threadIdx.x;
    int lo = g_cum[b * 257 + x];
    int hi = g_cum[b * 257 + x + 1];
    float* o = attn + ((size_t)(b * kTx + x)) * kTy + tid * 8;
    int t = tid * 8;
    float4 r;
    r.x = (t + 0 >= lo && t + 0 < hi) ? 1.f : 0.f;
    r.y = (t + 1 >= lo && t + 1 < hi) ? 1.f : 0.f;
    r.z = (t + 2 >= lo && t + 2 < hi) ? 1.f : 0.f;
    r.w = (t + 3 >= lo && t + 3 < hi) ? 1.f : 0.f;
    *(float4*)o = r;
    r.x = (t + 4 >= lo && t + 4 < hi) ? 1.f : 0.f;
    r.y = (t + 5 >= lo && t + 5 < hi) ? 1.f : 0.f;
    r.z = (t + 6 >= lo && t + 6 < hi) ? 1.f : 0.f;
    r.w = (t + 7 >= lo && t + 7 < hi) ? 1.f : 0.f;
    *(float4*)(o + 4) = r;
}

// ---------------- Kernel 4: o_en_ex gather -------------------------------------
__global__ void k_gather(const float* __restrict__ en, float* __restrict__ oex) {
    __shared__ __align__(16) float srow[kTx];
    __shared__ __align__(16) int   sidx[kTy];
    int h = blockIdx.x, b = blockIdx.y, tid = threadIdx.x;

    srow[tid] = en[((size_t)(b * kH + h)) * kTx + tid];
    const int* xsrc = g_xidx + b * kTy;
    for (int e = tid; e < kTy; e += 256) sidx[e] = xsrc[e];
    __syncthreads();

    float* o = oex + ((size_t)(b * kH + h)) * kTy + tid * 8;
    int4 ia = *(const int4*)&sidx[tid * 8];
    int4 ib = *(const int4*)&sidx[tid * 8 + 4];
    float4 r;
    r.x = (ia.x >= 0) ? srow[ia.x] : 0.f;
    r.y = (ia.y >= 0) ? srow[ia.y] : 0.f;
    r.z = (ia.z >= 0) ? srow[ia.z] : 0.f;
    r.w = (ia.w >= 0) ? srow[ia.w] : 0.f;
    *(float4*)o = r;
    r.x = (ib.x >= 0) ? srow[ib.x] : 0.f;
    r.y = (ib.y >= 0) ? srow[ib.y] : 0.f;
    r.z = (ib.z >= 0) ? srow[ib.z] : 0.f;
    r.w = (ib.w >= 0) ? srow[ib.w] : 0.f;
    *(float4*)(o + 4) = r;
}

// ---------------- launch --------------------------------------------------------
extern "C" void kernel_launch(void* const* d_in, const int* in_sizes, int n_in,
                              void* d_out, int out_size) {
    const float* en = (const float*)d_in[0];   // [B,H,Tx]
    const float* mu = (const float*)d_in[1];   // [B,C,Tx]
    const float* ls = (const float*)d_in[2];   // [B,C,Tx]
    const float* y  = (const float*)d_in[3];   // [B,Ty,C]
    const int*   xl = (const int*)d_in[4];     // [B]
    const int*   yl = (const int*)d_in[5];     // [B]

    float* out   = (float*)d_out;
    float* o_en  = out;                                     // B*H*Ty
    float* attn  = o_en + (size_t)kB * kH * kTy;            // B*Tx*Ty
    float* dr    = attn + (size_t)kB * kTx * kTy;           // B*Tx
    float* logp  = dr + (size_t)kB * kTx;                   // B*Tx*Ty

    cudaFuncSetAttribute(k_logp, cudaFuncAttributeMaxDynamicSharedMemorySize,
                         SMEM_ULL * 8);
    cudaFuncSetAttribute(k_mas, cudaFuncAttributeMaxDynamicSharedMemorySize, 65536);

    k_prep<<<kB, kTx>>>(mu, ls);
    k_logp<<<dim3(kTy / 128, kTx / 64, kB), 128, SMEM_ULL * 8>>>(y, logp);
    k_mas<<<kB, 256, 65536>>>(xl, yl, dr);
    k_attn<<<dim3(kTx, kB), 256>>>(attn);
    k_gather<<<dim3(kH, kB), 256>>>(en, o_en);
}